// round 1
// baseline (speedup 1.0000x reference)
#include <cuda_runtime.h>
#include <cstdint>

#define BB 8
#define MM 32
#define NCLS 80
#define RMAX 16
#define N0 25600
#define N1 6400
#define N2 1600
#define NTOT 33600
#define TOPKK 10

// ---------------- scratch (__device__ globals; no allocation) ----------------
__device__ float4 g_pb[BB * NTOT];                 // decoded pred boxes (image units)
__device__ unsigned long long g_best[BB * NTOT];   // packed (score_bits<<32 | (0xFFFFFFFF - m))
__device__ int g_fgcnt[BB];
__device__ int g_fglist[BB * 512];
__device__ float g_box[BB], g_dfl[BB], g_clspos[BB];
__device__ double g_sp[BB];

// ---------------- helpers ----------------
__device__ __forceinline__ void get_level(int n, const float* p0, const float* p1, const float* p2,
                                          const float* strides,
                                          const float*& p, int& HW, int& W, int& q, float& st) {
    if (n < N0)            { p = p0; HW = N0; W = 160; q = n;             st = strides[0]; }
    else if (n < N0 + N1)  { p = p1; HW = N1; W = 80;  q = n - N0;        st = strides[1]; }
    else                   { p = p2; HW = N2; W = 40;  q = n - (N0 + N1); st = strides[2]; }
}

__device__ __forceinline__ float ciou_f(float b1x1, float b1y1, float b1x2, float b1y2,
                                        float b2x1, float b2y1, float b2x2, float b2y2) {
    const float eps = 1e-7f;
    float w1 = b1x2 - b1x1, h1 = b1y2 - b1y1;
    float w2 = b2x2 - b2x1, h2 = b2y2 - b2y1;
    float iw = fminf(b1x2, b2x2) - fmaxf(b1x1, b2x1);
    float ih = fminf(b1y2, b2y2) - fmaxf(b1y1, b2y1);
    float inter = fmaxf(iw, 0.f) * fmaxf(ih, 0.f);
    float uni = w1 * h1 + w2 * h2 - inter + eps;
    float iou = inter / uni;
    float cw = fmaxf(b1x2, b2x2) - fminf(b1x1, b2x1);
    float ch = fmaxf(b1y2, b2y2) - fminf(b1y1, b2y1);
    float c2 = cw * cw + ch * ch + eps;
    float dx = b2x1 + b2x2 - b1x1 - b1x2;
    float dy = b2y1 + b2y2 - b1y1 - b1y2;
    float rho2 = (dx * dx + dy * dy) * 0.25f;
    float dat = atanf(w2 / (h2 + eps)) - atanf(w1 / (h1 + eps));
    float v = 0.4052847345693511f * dat * dat;
    float alpha = v / (v - iou + (1.f + eps));
    return iou - (rho2 / c2 + v * alpha);
}

__device__ __forceinline__ unsigned long long umax64(unsigned long long a, unsigned long long b) {
    return a > b ? a : b;
}

// ---------------- kernels ----------------
__global__ void k_init() {
    int i = blockIdx.x * blockDim.x + threadIdx.x;
    if (i < BB * NTOT) g_best[i] = 0xFFFFFFFFull;   // score=0.0f, m=0
    if (i < BB) {
        g_fgcnt[i] = 0;
        g_box[i] = 0.f; g_dfl[i] = 0.f; g_clspos[i] = 0.f;
        g_sp[i] = 0.0;
    }
}

// Decode pred boxes: softmax over 16 bins per side, dot with [0..15]
__global__ void k_decode(const float* __restrict__ p0, const float* __restrict__ p1,
                         const float* __restrict__ p2, const float* __restrict__ strides) {
    int idx = blockIdx.x * blockDim.x + threadIdx.x;
    if (idx >= BB * NTOT) return;
    int b = idx / NTOT, n = idx % NTOT;
    const float* p; int HW, W, q; float st;
    get_level(n, p0, p1, p2, strides, p, HW, W, q, st);
    float ax = (float)(q % W) + 0.5f;
    float ay = (float)(q / W) + 0.5f;
    float dist[4];
#pragma unroll
    for (int k = 0; k < 4; k++) {
        const float* base = p + ((size_t)b * 144 + k * 16) * HW + q;
        float x[16];
#pragma unroll
        for (int r = 0; r < 16; r++) x[r] = base[(size_t)r * HW];
        float mx = x[0];
#pragma unroll
        for (int r = 1; r < 16; r++) mx = fmaxf(mx, x[r]);
        float se = 0.f, sw = 0.f;
#pragma unroll
        for (int r = 0; r < 16; r++) {
            float e = expf(x[r] - mx);
            se += e; sw += e * (float)r;
        }
        dist[k] = sw / se;
    }
    float4 out;
    out.x = (ax - dist[0]) * st;
    out.y = (ay - dist[1]) * st;
    out.z = (ax + dist[2]) * st;
    out.w = (ay + dist[3]) * st;
    g_pb[idx] = out;
}

// TaskAlignedAssigner: one block per (b, m). Single pass: column-max of raw align
// + local top-10 (selection invariant under positive column scaling), then
// scatter normalized scores to per-anchor argmax keys.
__global__ void k_assign(const float* __restrict__ p0, const float* __restrict__ p1,
                         const float* __restrict__ p2,
                         const float* __restrict__ gt_boxes, const int* __restrict__ gt_labels,
                         const float* __restrict__ strides) {
    __shared__ unsigned long long sh_keys[256 * TOPKK];
    __shared__ unsigned long long sh_red[256];
    __shared__ float sh_fred[256];

    int bm = blockIdx.x;
    int b = bm >> 5, m = bm & 31;
    int tid = threadIdx.x;

    float gx1 = gt_boxes[(b * MM + m) * 4 + 0];
    float gy1 = gt_boxes[(b * MM + m) * 4 + 1];
    float gx2 = gt_boxes[(b * MM + m) * 4 + 2];
    float gy2 = gt_boxes[(b * MM + m) * 4 + 3];
    int label = gt_labels[b * MM + m];

    float tv[TOPKK]; int tn[TOPKK];
#pragma unroll
    for (int j = 0; j < TOPKK; j++) { tv[j] = 0.f; tn[j] = 0x7FFFFFFF; }
    float cmax = 0.f;

    for (int n = tid; n < NTOT; n += 256) {
        const float* p; int HW, W, q; float st;
        get_level(n, p0, p1, p2, strides, p, HW, W, q, st);
        float ax = ((float)(q % W) + 0.5f) * st;
        float ay = ((float)(q / W) + 0.5f) * st;
        if (ax < gx1 || ax > gx2 || ay < gy1 || ay > gy2) continue;
        float4 pbv = g_pb[b * NTOT + n];
        float iou = fmaxf(ciou_f(pbv.x, pbv.y, pbv.z, pbv.w, gx1, gy1, gx2, gy2), 0.f);
        float pcv = p[((size_t)b * 144 + 64 + label) * HW + q];
        float ps = 1.f / (1.f + expf(-pcv));
        float i2 = iou * iou;
        float align = ps * (i2 * i2 * i2);
        cmax = fmaxf(cmax, align);
        if (iou > 0.1f && align > 0.f) {
            bool beats = (align > tv[TOPKK - 1]) ||
                         (align == tv[TOPKK - 1] && n < tn[TOPKK - 1]);
            if (beats) {
                int j = TOPKK - 1;
                while (j > 0 && ((align > tv[j - 1]) || (align == tv[j - 1] && n < tn[j - 1]))) {
                    tv[j] = tv[j - 1]; tn[j] = tn[j - 1]; j--;
                }
                tv[j] = align; tn[j] = n;
            }
        }
    }

    // block-reduce column max (over raw align, pre-mask — matches reference)
    sh_fred[tid] = cmax;
    __syncthreads();
    for (int s = 128; s > 0; s >>= 1) {
        if (tid < s) sh_fred[tid] = fmaxf(sh_fred[tid], sh_fred[tid + s]);
        __syncthreads();
    }
    float colmax = sh_fred[0];
    __syncthreads();

    // publish local top-10 candidates as packable keys (tie-break: smaller n wins)
#pragma unroll
    for (int j = 0; j < TOPKK; j++) {
        unsigned long long key = 0ull;
        if (tv[j] > 0.f)
            key = ((unsigned long long)__float_as_uint(tv[j]) << 32) |
                  (unsigned long long)(0xFFFFFFFFu - (unsigned)tn[j]);
        sh_keys[tid * TOPKK + j] = key;
    }
    __syncthreads();

    // extract global top-10
    for (int iter = 0; iter < TOPKK; iter++) {
        unsigned long long loc = 0ull;
        for (int j = tid; j < 256 * TOPKK; j += 256) loc = umax64(loc, sh_keys[j]);
        sh_red[tid] = loc;
        __syncthreads();
        for (int s = 128; s > 0; s >>= 1) {
            if (tid < s) sh_red[tid] = umax64(sh_red[tid], sh_red[tid + s]);
            __syncthreads();
        }
        unsigned long long bestk = sh_red[0];
        __syncthreads();
        if (bestk != 0ull) {
#pragma unroll
            for (int j = 0; j < TOPKK; j++)
                if (sh_keys[tid * TOPKK + j] == bestk) sh_keys[tid * TOPKK + j] = 0ull;
            if (tid == 0) {
                float val = __uint_as_float((unsigned)(bestk >> 32));
                int n = (int)(0xFFFFFFFFu - (unsigned)(bestk & 0xFFFFFFFFull));
                float norm = val / (colmax + 1e-9f);
                unsigned long long okey =
                    ((unsigned long long)__float_as_uint(norm) << 32) |
                    (unsigned long long)(0xFFFFFFFFu - (unsigned)m);
                atomicMax(&g_best[b * NTOT + n], okey);
            }
        }
        __syncthreads();
    }
}

__global__ void k_collect() {
    int idx = blockIdx.x * blockDim.x + threadIdx.x;
    if (idx >= BB * NTOT) return;
    unsigned long long key = g_best[idx];
    float sc = __uint_as_float((unsigned)(key >> 32));
    if (sc > 0.f) {
        int b = idx / NTOT;
        int pos = atomicAdd(&g_fgcnt[b], 1);
        g_fglist[b * 512 + pos] = idx % NTOT;
    }
}

// Per-fg-anchor: box CIoU loss + DFL loss + positive class term
__global__ void k_fgloss(const float* __restrict__ p0, const float* __restrict__ p1,
                         const float* __restrict__ p2,
                         const float* __restrict__ gt_boxes, const int* __restrict__ gt_labels,
                         const float* __restrict__ strides) {
    int b = blockIdx.y;
    int i = blockIdx.x * blockDim.x + threadIdx.x;
    if (i >= g_fgcnt[b]) return;
    int n = g_fglist[b * 512 + i];
    unsigned long long key = g_best[b * NTOT + n];
    float score = __uint_as_float((unsigned)(key >> 32));
    int m = (int)(0xFFFFFFFFu - (unsigned)(key & 0xFFFFFFFFull));

    float gx1 = gt_boxes[(b * MM + m) * 4 + 0];
    float gy1 = gt_boxes[(b * MM + m) * 4 + 1];
    float gx2 = gt_boxes[(b * MM + m) * 4 + 2];
    float gy2 = gt_boxes[(b * MM + m) * 4 + 3];
    int label = gt_labels[b * MM + m];

    const float* p; int HW, W, q; float st;
    get_level(n, p0, p1, p2, strides, p, HW, W, q, st);
    float ax = (float)(q % W) + 0.5f;
    float ay = (float)(q / W) + 0.5f;

    float4 pbv = g_pb[b * NTOT + n];
    float boxl = 1.f - ciou_f(pbv.x, pbv.y, pbv.z, pbv.w, gx1, gy1, gx2, gy2);

    float t[4];
    t[0] = ax - gx1 / st;
    t[1] = ay - gy1 / st;
    t[2] = gx2 / st - ax;
    t[3] = gy2 / st - ay;

    float dfl = 0.f;
#pragma unroll
    for (int k = 0; k < 4; k++) {
        float tt = fminf(fmaxf(t[k], 0.f), 14.99f);
        int li = (int)floorf(tt);
        int ri = min(li + 1, 15);
        float wl = (float)ri - tt, wr = tt - (float)li;
        const float* base = p + ((size_t)b * 144 + k * 16) * HW + q;
        float x[16];
#pragma unroll
        for (int r = 0; r < 16; r++) x[r] = base[(size_t)r * HW];
        float mx = x[0];
#pragma unroll
        for (int r = 1; r < 16; r++) mx = fmaxf(mx, x[r]);
        float se = 0.f;
#pragma unroll
        for (int r = 0; r < 16; r++) se += expf(x[r] - mx);
        float lse = mx + logf(se);
        dfl += wl * (lse - x[li]) + wr * (lse - x[ri]);
    }

    float pcv = p[((size_t)b * 144 + 64 + label) * HW + q];

    atomicAdd(&g_box[b], boxl);
    atomicAdd(&g_dfl[b], dfl);
    atomicAdd(&g_clspos[b], pcv * score);
}

// Softplus (logaddexp(0,x)) sum over all class logits, per image.
__global__ void k_softplus(const float* __restrict__ p, int HW) {
    int b = blockIdx.y;
    const float* base = p + ((size_t)b * 144 + 64) * HW;
    int total = NCLS * HW;
    float acc = 0.f;
    for (int i = blockIdx.x * blockDim.x + threadIdx.x; i < total;
         i += gridDim.x * blockDim.x) {
        float x = base[i];
        acc += fmaxf(x, 0.f) + log1pf(expf(-fabsf(x)));
    }
    __shared__ double sred[256];
    sred[threadIdx.x] = (double)acc;
    __syncthreads();
    for (int s = 128; s > 0; s >>= 1) {
        if (threadIdx.x < s) sred[threadIdx.x] += sred[threadIdx.x + s];
        __syncthreads();
    }
    if (threadIdx.x == 0) atomicAdd(&g_sp[b], sred[0]);
}

__global__ void k_final(float* out) {
    if (threadIdx.x != 0 || blockIdx.x != 0) return;
    double total = 0.0;
    for (int b = 0; b < BB; b++) {
        int cnt = g_fgcnt[b];
        double has = cnt > 0 ? 1.0 : 0.0;
        double nf = cnt > 0 ? (double)cnt : 1.0;
        double bl = (double)g_box[b] / nf;
        double dl = (double)g_dfl[b] / (nf * 4.0);
        double cl = (g_sp[b] - (double)g_clspos[b]) / (double)NTOT;
        total += 7.5 * bl * has + 0.5 * cl * has + 1.5 * dl * has;
    }
    out[0] = (float)total;
}

// ---------------- launch ----------------
extern "C" void kernel_launch(void* const* d_in, const int* in_sizes, int n_in,
                              void* d_out, int out_size) {
    const float* p0 = (const float*)d_in[0];
    const float* p1 = (const float*)d_in[1];
    const float* p2 = (const float*)d_in[2];
    const float* gtb = (const float*)d_in[3];
    const int* gtl = (const int*)d_in[4];
    const float* strides = (const float*)d_in[5];
    float* out = (float*)d_out;

    int nthreads = BB * NTOT;
    int nblk = (nthreads + 255) / 256;

    k_init<<<nblk, 256>>>();
    k_decode<<<nblk, 256>>>(p0, p1, p2, strides);
    k_assign<<<BB * MM, 256>>>(p0, p1, p2, gtb, gtl, strides);
    k_collect<<<nblk, 256>>>();
    k_fgloss<<<dim3(8, BB), 64>>>(p0, p1, p2, gtb, gtl, strides);
    k_softplus<<<dim3(128, BB), 256>>>(p0, N0);
    k_softplus<<<dim3(32, BB), 256>>>(p1, N1);
    k_softplus<<<dim3(8, BB), 256>>>(p2, N2);
    k_final<<<1, 1>>>(out);
}

// round 2
// speedup vs baseline: 2.7671x; 2.7671x over previous
#include <cuda_runtime.h>
#include <cstdint>

#define BB 8
#define MM 32
#define NCLS 80
#define N0 25600
#define N1 6400
#define N2 1600
#define NTOT 33600
#define TOPKK 10
#define QTOT 8400          // NTOT/4 (float4 anchors per image)
#define BLK_PER_IMG 33     // ceil(8400/256)

// ---------------- scratch ----------------
__device__ float4 g_pb[BB * NTOT];                 // decoded pred boxes (image units)
__device__ unsigned long long g_best[BB * NTOT];   // (score_bits<<32 | (0xFFFFFFFF - m))
__device__ double g_sp_part[BB * BLK_PER_IMG];     // softplus block partials
__device__ int g_fgcnt[BB];
__device__ float g_box[BB], g_dfl[BB], g_clspos[BB];

// ---------------- helpers ----------------
__device__ __forceinline__ float ciou_f(float b1x1, float b1y1, float b1x2, float b1y2,
                                        float b2x1, float b2y1, float b2x2, float b2y2) {
    const float eps = 1e-7f;
    float w1 = b1x2 - b1x1, h1 = b1y2 - b1y1;
    float w2 = b2x2 - b2x1, h2 = b2y2 - b2y1;
    float iw = fminf(b1x2, b2x2) - fmaxf(b1x1, b2x1);
    float ih = fminf(b1y2, b2y2) - fmaxf(b1y1, b2y1);
    float inter = fmaxf(iw, 0.f) * fmaxf(ih, 0.f);
    float uni = w1 * h1 + w2 * h2 - inter + eps;
    float iou = inter / uni;
    float cw = fmaxf(b1x2, b2x2) - fminf(b1x1, b2x1);
    float ch = fmaxf(b1y2, b2y2) - fminf(b1y1, b2y1);
    float c2 = cw * cw + ch * ch + eps;
    float dx = b2x1 + b2x2 - b1x1 - b1x2;
    float dy = b2y1 + b2y2 - b1y1 - b1y2;
    float rho2 = (dx * dx + dy * dy) * 0.25f;
    float dat = atanf(w2 / (h2 + eps)) - atanf(w1 / (h1 + eps));
    float v = 0.4052847345693511f * dat * dat;
    float alpha = v / (v - iou + (1.f + eps));
    return iou - (rho2 / c2 + v * alpha);
}

__device__ __forceinline__ unsigned long long umax64(unsigned long long a, unsigned long long b) {
    return a > b ? a : b;
}

// ================= k_main: fused decode + softplus + init (one pass over 155MB) ==========
__global__ void __launch_bounds__(256) k_main(
        const float* __restrict__ p0, const float* __restrict__ p1,
        const float* __restrict__ p2, const float* __restrict__ strides) {
    int b = blockIdx.y;
    int j = blockIdx.x * 256 + threadIdx.x;     // float4-anchor index within image

    // zero per-image scalars (k_fg / k_final run later; safe ordering)
    if (blockIdx.x == 0 && threadIdx.x == 0) {
        g_fgcnt[b] = 0; g_box[b] = 0.f; g_dfl[b] = 0.f; g_clspos[b] = 0.f;
    }

    float acc = 0.f;   // softplus partial (this thread)

    if (j < QTOT) {
        const float* p; int HW, W, q4, noff; float st;
        if (j < 6400)      { p = p0; HW = N0; W = 160; q4 = j;        noff = 0;       st = strides[0]; }
        else if (j < 8000) { p = p1; HW = N1; W = 80;  q4 = j - 6400; noff = N0;      st = strides[1]; }
        else               { p = p2; HW = N2; W = 40;  q4 = j - 8000; noff = N0 + N1; st = strides[2]; }
        int q = q4 * 4;
        float ay = (float)(q / W) + 0.5f;
        float ax = (float)(q % W) + 0.5f;      // anchors ax, ax+1, ax+2, ax+3

        const float* pb = p + (size_t)b * 144 * HW + q;

        // ---- decode 4 anchors: softmax(16)·proj per side (no max-sub; |x|<~6) ----
        float4 out[4];
#pragma unroll
        for (int k = 0; k < 4; k++) {
            float se0 = 0.f, se1 = 0.f, se2 = 0.f, se3 = 0.f;
            float sw0 = 0.f, sw1 = 0.f, sw2 = 0.f, sw3 = 0.f;
#pragma unroll
            for (int r = 0; r < 16; r++) {
                float4 v = *(const float4*)(pb + (size_t)(k * 16 + r) * HW);
                float e0 = __expf(v.x), e1 = __expf(v.y), e2 = __expf(v.z), e3 = __expf(v.w);
                float fr = (float)r;
                se0 += e0; sw0 = fmaf(e0, fr, sw0);
                se1 += e1; sw1 = fmaf(e1, fr, sw1);
                se2 += e2; sw2 = fmaf(e2, fr, sw2);
                se3 += e3; sw3 = fmaf(e3, fr, sw3);
            }
            float d0 = sw0 / se0, d1 = sw1 / se1, d2 = sw2 / se2, d3 = sw3 / se3;
            if (k == 0) { out[0].x = (ax - d0) * st;        out[1].x = (ax + 1.f - d1) * st;
                          out[2].x = (ax + 2.f - d2) * st;  out[3].x = (ax + 3.f - d3) * st; }
            if (k == 1) { out[0].y = (ay - d0) * st; out[1].y = (ay - d1) * st;
                          out[2].y = (ay - d2) * st; out[3].y = (ay - d3) * st; }
            if (k == 2) { out[0].z = (ax + d0) * st;        out[1].z = (ax + 1.f + d1) * st;
                          out[2].z = (ax + 2.f + d2) * st;  out[3].z = (ax + 3.f + d3) * st; }
            if (k == 3) { out[0].w = (ay + d0) * st; out[1].w = (ay + d1) * st;
                          out[2].w = (ay + d2) * st; out[3].w = (ay + d3) * st; }
        }
        int base = b * NTOT + noff + q;
#pragma unroll
        for (int a = 0; a < 4; a++) {
            g_pb[base + a] = out[a];
            g_best[base + a] = 0xFFFFFFFFull;   // score 0, m = 0
        }

        // ---- softplus over 80 class channels, product trick ----
        const float* pc = p + ((size_t)b * 144 + 64) * HW + q;
        float P0 = 1.f, P1 = 1.f, P2 = 1.f, P3 = 1.f;
#pragma unroll 4
        for (int c = 0; c < NCLS; c++) {
            float4 v = *(const float4*)(pc + (size_t)c * HW);
            acc += fmaxf(v.x, 0.f) + fmaxf(v.y, 0.f) + fmaxf(v.z, 0.f) + fmaxf(v.w, 0.f);
            P0 *= 1.f + __expf(-fabsf(v.x));
            P1 *= 1.f + __expf(-fabsf(v.y));
            P2 *= 1.f + __expf(-fabsf(v.z));
            P3 *= 1.f + __expf(-fabsf(v.w));
            if ((c & 15) == 15) {   // flush every 64 terms (each <= 2 -> P <= 2^64, safe)
                acc += __logf((P0 * P1) * (P2 * P3));
                P0 = P1 = P2 = P3 = 1.f;
            }
        }
    }

    // block reduction of softplus partial -> dense per-block slot (no atomics, no init needed)
    __shared__ double sred[256];
    sred[threadIdx.x] = (double)acc;
    __syncthreads();
    for (int s = 128; s > 0; s >>= 1) {
        if (threadIdx.x < s) sred[threadIdx.x] += sred[threadIdx.x + s];
        __syncthreads();
    }
    if (threadIdx.x == 0) g_sp_part[b * BLK_PER_IMG + blockIdx.x] = sred[0];
}

// ================= k_assign: one block per (b,m), rect scan =================
__global__ void __launch_bounds__(256) k_assign(
        const float* __restrict__ p0, const float* __restrict__ p1,
        const float* __restrict__ p2,
        const float* __restrict__ gt_boxes, const int* __restrict__ gt_labels,
        const float* __restrict__ strides) {
    __shared__ unsigned long long sh_keys[256 * TOPKK];
    __shared__ unsigned long long sh_red[256];
    __shared__ float sh_fred[256];

    int bm = blockIdx.x;
    int b = bm >> 5, m = bm & 31;
    int tid = threadIdx.x;

    float gx1 = gt_boxes[(b * MM + m) * 4 + 0];
    float gy1 = gt_boxes[(b * MM + m) * 4 + 1];
    float gx2 = gt_boxes[(b * MM + m) * 4 + 2];
    float gy2 = gt_boxes[(b * MM + m) * 4 + 3];
    int label = gt_labels[b * MM + m];

    float tv[TOPKK]; int tn[TOPKK];
#pragma unroll
    for (int jj = 0; jj < TOPKK; jj++) { tv[jj] = 0.f; tn[jj] = 0x7FFFFFFF; }
    float cmax = 0.f;

#pragma unroll
    for (int lvl = 0; lvl < 3; lvl++) {
        const float* p; int HW, W, noff; float st;
        if (lvl == 0)      { p = p0; HW = N0; W = 160; noff = 0;       st = strides[0]; }
        else if (lvl == 1) { p = p1; HW = N1; W = 80;  noff = N0;      st = strides[1]; }
        else               { p = p2; HW = N2; W = 40;  noff = N0 + N1; st = strides[2]; }

        float inv = 1.f / st;
        int x0 = max(0, (int)(gx1 * inv - 0.5f) - 1);
        int x1 = min(W - 1, (int)(gx2 * inv - 0.5f) + 1);
        int y0 = max(0, (int)(gy1 * inv - 0.5f) - 1);
        int y1 = min(W - 1, (int)(gy2 * inv - 0.5f) + 1);
        int rw = x1 - x0 + 1, rh = y1 - y0 + 1;
        if (rw <= 0 || rh <= 0) continue;
        int tot = rw * rh;
        const float* pcl = p + ((size_t)b * 144 + 64 + label) * HW;

        for (int i = tid; i < tot; i += 256) {
            int qx = x0 + i % rw;
            int qy = y0 + i / rw;
            float ax = ((float)qx + 0.5f) * st;
            float ay = ((float)qy + 0.5f) * st;
            if (ax < gx1 || ax > gx2 || ay < gy1 || ay > gy2) continue;
            int q = qy * W + qx;
            int n = noff + q;
            float4 pbv = g_pb[b * NTOT + n];
            float iou = fmaxf(ciou_f(pbv.x, pbv.y, pbv.z, pbv.w, gx1, gy1, gx2, gy2), 0.f);
            float pcv = pcl[q];
            float ps = 1.f / (1.f + __expf(-pcv));
            float i2 = iou * iou;
            float align = ps * (i2 * i2 * i2);
            cmax = fmaxf(cmax, align);
            if (iou > 0.1f && align > 0.f &&
                ((align > tv[TOPKK - 1]) ||
                 (align == tv[TOPKK - 1] && n < tn[TOPKK - 1]))) {
                // unrolled compare-swap insertion (static indices -> registers)
                float cv = align; int cn = n;
#pragma unroll
                for (int jj = 0; jj < TOPKK; jj++) {
                    bool bt = (cv > tv[jj]) || (cv == tv[jj] && cn < tn[jj]);
                    float nv = bt ? cv : tv[jj];  int nn = bt ? cn : tn[jj];
                    cv = bt ? tv[jj] : cv;        cn = bt ? tn[jj] : cn;
                    tv[jj] = nv;                  tn[jj] = nn;
                }
            }
        }
    }

    // block-reduce column max (raw align, pre-mask — matches reference)
    sh_fred[tid] = cmax;
    __syncthreads();
    for (int s = 128; s > 0; s >>= 1) {
        if (tid < s) sh_fred[tid] = fmaxf(sh_fred[tid], sh_fred[tid + s]);
        __syncthreads();
    }
    float colmax = sh_fred[0];
    __syncthreads();

#pragma unroll
    for (int jj = 0; jj < TOPKK; jj++) {
        unsigned long long key = 0ull;
        if (tv[jj] > 0.f)
            key = ((unsigned long long)__float_as_uint(tv[jj]) << 32) |
                  (unsigned long long)(0xFFFFFFFFu - (unsigned)tn[jj]);
        sh_keys[tid * TOPKK + jj] = key;
    }
    __syncthreads();

    for (int iter = 0; iter < TOPKK; iter++) {
        unsigned long long loc = 0ull;
        for (int jj = tid; jj < 256 * TOPKK; jj += 256) loc = umax64(loc, sh_keys[jj]);
        sh_red[tid] = loc;
        __syncthreads();
        for (int s = 128; s > 0; s >>= 1) {
            if (tid < s) sh_red[tid] = umax64(sh_red[tid], sh_red[tid + s]);
            __syncthreads();
        }
        unsigned long long bestk = sh_red[0];
        __syncthreads();
        if (bestk != 0ull) {
#pragma unroll
            for (int jj = 0; jj < TOPKK; jj++)
                if (sh_keys[tid * TOPKK + jj] == bestk) sh_keys[tid * TOPKK + jj] = 0ull;
            if (tid == 0) {
                float val = __uint_as_float((unsigned)(bestk >> 32));
                int n = (int)(0xFFFFFFFFu - (unsigned)(bestk & 0xFFFFFFFFull));
                float norm = val / (colmax + 1e-9f);
                unsigned long long okey =
                    ((unsigned long long)__float_as_uint(norm) << 32) |
                    (unsigned long long)(0xFFFFFFFFu - (unsigned)m);
                atomicMax(&g_best[b * NTOT + n], okey);
            }
        }
        __syncthreads();
    }
}

// ================= k_fg: scan g_best, compute fg losses inline =================
__global__ void __launch_bounds__(256) k_fg(
        const float* __restrict__ p0, const float* __restrict__ p1,
        const float* __restrict__ p2,
        const float* __restrict__ gt_boxes, const int* __restrict__ gt_labels,
        const float* __restrict__ strides) {
    int idx = blockIdx.x * 256 + threadIdx.x;
    if (idx >= BB * NTOT) return;
    unsigned long long key = g_best[idx];
    float score = __uint_as_float((unsigned)(key >> 32));
    if (score <= 0.f) return;

    int b = idx / NTOT, n = idx % NTOT;
    int m = (int)(0xFFFFFFFFu - (unsigned)(key & 0xFFFFFFFFull));
    atomicAdd(&g_fgcnt[b], 1);

    float gx1 = gt_boxes[(b * MM + m) * 4 + 0];
    float gy1 = gt_boxes[(b * MM + m) * 4 + 1];
    float gx2 = gt_boxes[(b * MM + m) * 4 + 2];
    float gy2 = gt_boxes[(b * MM + m) * 4 + 3];
    int label = gt_labels[b * MM + m];

    const float* p; int HW, W, q; float st;
    if (n < N0)           { p = p0; HW = N0; W = 160; q = n;             st = strides[0]; }
    else if (n < N0 + N1) { p = p1; HW = N1; W = 80;  q = n - N0;        st = strides[1]; }
    else                  { p = p2; HW = N2; W = 40;  q = n - (N0 + N1); st = strides[2]; }
    float ax = (float)(q % W) + 0.5f;
    float ay = (float)(q / W) + 0.5f;

    float4 pbv = g_pb[idx];
    float boxl = 1.f - ciou_f(pbv.x, pbv.y, pbv.z, pbv.w, gx1, gy1, gx2, gy2);

    float t[4];
    t[0] = ax - gx1 / st;
    t[1] = ay - gy1 / st;
    t[2] = gx2 / st - ax;
    t[3] = gy2 / st - ay;

    float dfl = 0.f;
#pragma unroll
    for (int k = 0; k < 4; k++) {
        float tt = fminf(fmaxf(t[k], 0.f), 14.99f);
        int li = (int)floorf(tt);
        int ri = min(li + 1, 15);
        float wl = (float)ri - tt, wr = tt - (float)li;
        const float* base = p + ((size_t)b * 144 + k * 16) * HW + q;
        float x[16];
#pragma unroll
        for (int r = 0; r < 16; r++) x[r] = base[(size_t)r * HW];
        float mx = x[0];
#pragma unroll
        for (int r = 1; r < 16; r++) mx = fmaxf(mx, x[r]);
        float se = 0.f;
#pragma unroll
        for (int r = 0; r < 16; r++) se += expf(x[r] - mx);
        float lse = mx + logf(se);
        dfl += wl * (lse - x[li]) + wr * (lse - x[ri]);
    }

    float pcv = p[((size_t)b * 144 + 64 + label) * HW + q];

    atomicAdd(&g_box[b], boxl);
    atomicAdd(&g_dfl[b], dfl);
    atomicAdd(&g_clspos[b], pcv * score);
}

// ================= k_final =================
__global__ void k_final(float* out) {
    __shared__ double s[BB];
    int tid = threadIdx.x;
    if (tid < BB) {
        double sp = 0.0;
        for (int i = 0; i < BLK_PER_IMG; i++) sp += g_sp_part[tid * BLK_PER_IMG + i];
        int cnt = g_fgcnt[tid];
        double has = cnt > 0 ? 1.0 : 0.0;
        double nf = cnt > 0 ? (double)cnt : 1.0;
        double bl = (double)g_box[tid] / nf;
        double dl = (double)g_dfl[tid] / (nf * 4.0);
        double cl = (sp - (double)g_clspos[tid]) / (double)NTOT;
        s[tid] = (7.5 * bl + 0.5 * cl + 1.5 * dl) * has;
    }
    __syncthreads();
    if (tid == 0) {
        double total = 0.0;
        for (int b = 0; b < BB; b++) total += s[b];
        out[0] = (float)total;
    }
}

// ---------------- launch ----------------
extern "C" void kernel_launch(void* const* d_in, const int* in_sizes, int n_in,
                              void* d_out, int out_size) {
    const float* p0 = (const float*)d_in[0];
    const float* p1 = (const float*)d_in[1];
    const float* p2 = (const float*)d_in[2];
    const float* gtb = (const float*)d_in[3];
    const int* gtl = (const int*)d_in[4];
    const float* strides = (const float*)d_in[5];
    float* out = (float*)d_out;

    k_main<<<dim3(BLK_PER_IMG, BB), 256>>>(p0, p1, p2, strides);
    k_assign<<<BB * MM, 256>>>(p0, p1, p2, gtb, gtl, strides);
    k_fg<<<(BB * NTOT + 255) / 256, 256>>>(p0, p1, p2, gtb, gtl, strides);
    k_final<<<1, 32>>>(out);
}